// round 17
// baseline (speedup 1.0000x reference)
#include <cuda_runtime.h>
#include <cuda_fp16.h>
#include <cstdint>
#include <math.h>

#define NWIN 2048
#define NTOK 64
#define CDIM 384
#define NH   12
#define HD   32
#define MTOT (NWIN * NTOK)

// ---------------------------------------------------------------------------
// Device scratch
// ---------------------------------------------------------------------------
__device__ __half g_x16[(size_t)MTOT * CDIM];
__device__ __half g_attn16[(size_t)MTOT * CDIM];
__device__ float  g_bias[NH * NTOK * NTOK];
__device__ __half g_wt_qkv2h[(size_t)NH * 96 * CDIM];   // head-grouped [h][q|k|v][384]
__device__ __half g_wt_projh[(size_t)CDIM * CDIM];      // [384][384] K-major

__device__ __forceinline__ uint32_t h2u(__half2 h) { return *reinterpret_cast<uint32_t*>(&h); }

__device__ __forceinline__ void mma_f16(float* d, uint32_t a0, uint32_t a1, uint32_t a2,
                                        uint32_t a3, uint32_t b0, uint32_t b1) {
    asm volatile(
        "mma.sync.aligned.m16n8k16.row.col.f32.f16.f16.f32 "
        "{%0,%1,%2,%3}, {%4,%5,%6,%7}, {%8,%9}, {%0,%1,%2,%3};"
        : "+f"(d[0]), "+f"(d[1]), "+f"(d[2]), "+f"(d[3])
        : "r"(a0), "r"(a1), "r"(a2), "r"(a3), "r"(b0), "r"(b1));
}
__device__ __forceinline__ void ldsm4(uint32_t* r, uint32_t addr) {
    asm volatile("ldmatrix.sync.aligned.m8n8.x4.shared.b16 {%0,%1,%2,%3}, [%4];"
                 : "=r"(r[0]), "=r"(r[1]), "=r"(r[2]), "=r"(r[3]) : "r"(addr));
}
__device__ __forceinline__ uint32_t smem_u32(const void* p) {
    uint32_t a;
    asm("{ .reg .u64 t; cvta.to.shared.u64 t, %1; cvt.u32.u64 %0, t; }" : "=r"(a) : "l"(p));
    return a;
}
__device__ __forceinline__ void cp16(uint32_t dst, const void* src) {
    asm volatile("cp.async.cg.shared.global [%0], [%1], 16;" :: "r"(dst), "l"(src));
}
#define CP_COMMIT() asm volatile("cp.async.commit_group;" ::: "memory")
#define CP_WAIT(N)  asm volatile("cp.async.wait_group %0;" :: "n"(N) : "memory")

// ---------------------------------------------------------------------------
// MERGED prep kernel: convert_x (16 elems/thread, .cs reads) | transpose_qkv |
// transpose_proj | bias table.
// ---------------------------------------------------------------------------
#define CONV_BLOCKS (MTOT * CDIM / 16 / 256)   // 12288
#define TQ_BLOCKS   (36 * 12)                   // 432
#define TP_BLOCKS   (12 * 12)                   // 144
#define BIAS_BLOCKS 16
#define PREP_BLOCKS (CONV_BLOCKS + TQ_BLOCKS + TP_BLOCKS + BIAS_BLOCKS)

__global__ void __launch_bounds__(256)
prep_kernel(const float* __restrict__ x, const float* __restrict__ qkv_w,
            const float* __restrict__ proj_w,
            const float* __restrict__ w1, const float* __restrict__ b1,
            const float* __restrict__ w2, const float* __restrict__ b2) {
    __shared__ float tl[32][33];
    __shared__ float sw1[192], sb1[64], sw2[768], sb2[12];
    const int b = blockIdx.x;
    const int t = threadIdx.x;

    if (b < CONV_BLOCKS) {
        size_t i = ((size_t)b * 256 + t) * 16;
#pragma unroll
        for (int u = 0; u < 2; u++) {
            size_t j = i + u * 8;
            float4 v0 = __ldcs((const float4*)(x + j));
            float4 v1 = __ldcs((const float4*)(x + j + 4));
            uint4 o;
            o.x = h2u(__floats2half2_rn(v0.x, v0.y));
            o.y = h2u(__floats2half2_rn(v0.z, v0.w));
            o.z = h2u(__floats2half2_rn(v1.x, v1.y));
            o.w = h2u(__floats2half2_rn(v1.z, v1.w));
            *(uint4*)(g_x16 + j) = o;
        }
    } else if (b < CONV_BLOCKS + TQ_BLOCKS) {
        int bb = b - CONV_BLOCKS;
        int n0 = (bb % 36) * 32, k0 = (bb / 36) * 32;
        int xx = t & 31, yy = t >> 5;
#pragma unroll
        for (int j = yy; j < 32; j += 8) tl[j][xx] = qkv_w[(size_t)(k0 + j) * (3 * CDIM) + n0 + xx];
        __syncthreads();
        int part = n0 / CDIM;
        int h    = (n0 % CDIM) / 32;
        int rbase = h * 96 + part * 32;
#pragma unroll
        for (int j = yy; j < 32; j += 8)
            g_wt_qkv2h[(size_t)(rbase + j) * CDIM + k0 + xx] = __float2half_rn(tl[xx][j]);
    } else if (b < CONV_BLOCKS + TQ_BLOCKS + TP_BLOCKS) {
        int bb = b - CONV_BLOCKS - TQ_BLOCKS;
        int n0 = (bb % 12) * 32, k0 = (bb / 12) * 32;
        int xx = t & 31, yy = t >> 5;
#pragma unroll
        for (int j = yy; j < 32; j += 8) tl[j][xx] = proj_w[(size_t)(k0 + j) * CDIM + n0 + xx];
        __syncthreads();
#pragma unroll
        for (int j = yy; j < 32; j += 8)
            g_wt_projh[(size_t)(n0 + j) * CDIM + k0 + xx] = __float2half_rn(tl[xx][j]);
    } else {
        if (t < 192) sw1[t] = w1[t];
        if (t < 64)  sb1[t] = b1[t];
        for (int i = t; i < 768; i += 256) sw2[i] = w2[i];
        if (t < 12)  sb2[t] = b2[t];
        __syncthreads();

        int idx = (b - CONV_BLOCKS - TQ_BLOCKS - TP_BLOCKS) * 256 + t;
        if (idx >= NTOK * NTOK) return;
        int n = idx / NTOK, m = idx % NTOK;
        float r0 = (float)((n >> 4) & 3) - (float)((m >> 4) & 3);
        float r1 = (float)((n >> 2) & 3) - (float)((m >> 2) & 3);
        float r2 = (float)(n & 3)        - (float)(m & 3);

        float outh[NH];
#pragma unroll
        for (int h = 0; h < NH; h++) outh[h] = sb2[h];
        for (int j = 0; j < 64; j++) {
            float hj = fmaf(r0, sw1[j], fmaf(r1, sw1[64 + j], fmaf(r2, sw1[128 + j], sb1[j])));
            hj = fmaxf(hj, 0.0f);
#pragma unroll
            for (int h = 0; h < NH; h++) outh[h] = fmaf(hj, sw2[j * NH + h], outh[h]);
        }
#pragma unroll
        for (int h = 0; h < NH; h++) g_bias[h * NTOK * NTOK + idx] = outh[h];
    }
}

// ---------------------------------------------------------------------------
// FUSED fp16 QKV-GEMM + attention: 128 threads/4 warps, warp 64x48 (2Mx2N),
// 2-stage cp.async ring, occ 3. Bias slice prefetched to smem during GEMM.
// smem: A ring 0..32768, B ring 32768..57344, bias 57344..74752 (64x68 fp32).
// Attn staging reuses A-ring: qs 2x[64][40] @0, ks @10240B, vt 2x[32][72] @20480B.
// ---------------------------------------------------------------------------
#define NCH 6
#define BIAS_OFF 57344
#define FUSED_SMEM 74752

__global__ void __launch_bounds__(128, 3)
qkv_attn_kernel(const __half* __restrict__ A, const float* __restrict__ qkv_b) {
    extern __shared__ float dsm[];
    __half* hsm = (__half*)dsm;

    const int t    = threadIdx.x;
    const int wid  = t >> 5, lane = t & 31;
    const int wm   = wid >> 1;
    const int wnn  = wid & 1;
    const int h    = blockIdx.x;
    const int m0   = blockIdx.y * 128;
    const int lrow = lane >> 2;
    const int lcol = lane & 3;

    const uint32_t sbase = smem_u32(dsm);
    const __half* Bt = g_wt_qkv2h + (size_t)h * 96 * CDIM;

    float acc[4][6][4];
#pragma unroll
    for (int i = 0; i < 4; i++)
#pragma unroll
        for (int j = 0; j < 6; j++)
#pragma unroll
            for (int r = 0; r < 4; r++) acc[i][j][r] = 0.0f;

    const int ldr = t >> 3;
    const int ldg = t & 7;

    const int grp = lane >> 3, lr8 = lane & 7;
    const int rsel = (grp & 1) * 8;
    const int ksel = grp >> 1;

    uint32_t aoff[4]; int arl[4];
#pragma unroll
    for (int mt = 0; mt < 4; mt++) {
        int r = wm * 64 + mt * 16 + rsel + lr8;
        aoff[mt] = (uint32_t)(r << 7);
        arl[mt]  = r & 7;
    }
    uint32_t boff[3]; int brl[3];
#pragma unroll
    for (int p = 0; p < 3; p++) {
        int r = wnn * 48 + p * 16 + rsel + lr8;
        boff[p] = (uint32_t)(r << 7);
        brl[p]  = r & 7;
    }

#define ISSUE(ch, st) do {                                                              \
        int _k0 = (ch) * 64;                                                            \
        _Pragma("unroll")                                                               \
        for (int _i = 0; _i < 8; _i++) {                                                \
            int _row = ldr + _i * 16;                                                   \
            int _sg  = ldg ^ (_row & 7);                                                \
            cp16(sbase + (st) * 16384 + (uint32_t)((_row << 7) + (_sg << 4)),           \
                 A + (size_t)(m0 + _row) * CDIM + _k0 + ldg * 8);                       \
        }                                                                               \
        _Pragma("unroll")                                                               \
        for (int _i = 0; _i < 6; _i++) {                                                \
            int _row = ldr + _i * 16;                                                   \
            int _sg  = ldg ^ (_row & 7);                                                \
            cp16(sbase + 32768 + (st) * 12288 + (uint32_t)((_row << 7) + (_sg << 4)),   \
                 Bt + (size_t)_row * CDIM + _k0 + ldg * 8);                             \
        }                                                                               \
        CP_COMMIT();                                                                    \
    } while (0)

#define COMPUTE(st) do {                                                                \
        const uint32_t Aab = sbase + (st) * 16384;                                      \
        const uint32_t Bab = sbase + 32768 + (st) * 12288;                              \
        _Pragma("unroll")                                                               \
        for (int ks = 0; ks < 4; ks++) {                                                \
            uint32_t afr[4][4], bfr[3][4];                                              \
            _Pragma("unroll")                                                           \
            for (int mt = 0; mt < 4; mt++)                                              \
                ldsm4(afr[mt], Aab + aoff[mt] +                                         \
                      (uint32_t)(((2 * ks + ksel) ^ arl[mt]) << 4));                    \
            _Pragma("unroll")                                                           \
            for (int p = 0; p < 3; p++)                                                 \
                ldsm4(bfr[p], Bab + boff[p] +                                           \
                      (uint32_t)(((2 * ks + ksel) ^ brl[p]) << 4));                     \
            _Pragma("unroll")                                                           \
            for (int mt = 0; mt < 4; mt++) {                                            \
                _Pragma("unroll")                                                       \
                for (int p = 0; p < 3; p++) {                                           \
                    mma_f16(acc[mt][2 * p],     afr[mt][0], afr[mt][1], afr[mt][2],     \
                            afr[mt][3], bfr[p][0], bfr[p][2]);                          \
                    mma_f16(acc[mt][2 * p + 1], afr[mt][0], afr[mt][1], afr[mt][2],     \
                            afr[mt][3], bfr[p][1], bfr[p][3]);                          \
                }                                                                       \
            }                                                                           \
        }                                                                               \
    } while (0)

#define STEP(c) do {                                                                    \
        if ((c) == NCH - 1) { CP_WAIT(0); } else { CP_WAIT(1); }                        \
        __syncthreads();                                                                \
        COMPUTE((c) & 1);                                                               \
        __syncthreads();                                                                \
        if ((c) + 2 < NCH) ISSUE((c) + 2, (c) & 1);                                     \
    } while (0)

    // ---- bias slice prefetch (joins ISSUE(0)'s commit group)
    {
        const float* bh = g_bias + h * NTOK * NTOK;
#pragma unroll
        for (int i = 0; i < 8; i++) {
            int idx = t + i * 128;           // 0..1023 chunks of 16B
            int row = idx >> 4, g = idx & 15;
            cp16(sbase + BIAS_OFF + (uint32_t)(row * 272 + g * 16),
                 bh + row * 64 + g * 4);
        }
    }
    ISSUE(0, 0);
    ISSUE(1, 1);
    STEP(0); STEP(1); STEP(2); STEP(3); STEP(4); STEP(5);

    // ---- epilogue: stage q/k/v (+bias, fp16) into smem union
    __half* qsh = hsm;                 // 2 x [64][40]
    __half* ksh = hsm + 5120;
    __half* vth = hsm + 10240;         // 2 x [32][72]
#pragma unroll
    for (int mt = 0; mt < 4; mt++) {
#pragma unroll
        for (int nt = 0; nt < 6; nt++) {
            int row = wm * 64 + mt * 16 + lrow;
            int col = wnn * 48 + nt * 8 + lcol * 2;
            int part = col >> 5, c = col & 31;
            float2 bv = *(const float2*)(qkv_b + part * CDIM + h * HD + c);
            int tm = row >> 6, r64 = row & 63;
            if (part == 2) {
                __half* v_ = vth + tm * 2304;
                v_[c * 72 + r64]           = __float2half_rn(acc[mt][nt][0] + bv.x);
                v_[(c + 1) * 72 + r64]     = __float2half_rn(acc[mt][nt][1] + bv.y);
                v_[c * 72 + r64 + 8]       = __float2half_rn(acc[mt][nt][2] + bv.x);
                v_[(c + 1) * 72 + r64 + 8] = __float2half_rn(acc[mt][nt][3] + bv.y);
            } else {
                uint32_t p0 = h2u(__floats2half2_rn(acc[mt][nt][0] + bv.x,
                                                    acc[mt][nt][1] + bv.y));
                uint32_t p1 = h2u(__floats2half2_rn(acc[mt][nt][2] + bv.x,
                                                    acc[mt][nt][3] + bv.y));
                __half* d_ = (part == 0 ? qsh : ksh) + tm * 2560;
                *(uint32_t*)(d_ + r64 * 40 + c)       = p0;
                *(uint32_t*)(d_ + (r64 + 8) * 40 + c) = p1;
            }
        }
    }
    __syncthreads();

    // ---- attention: 2 warps per window
    const int team = wid >> 1;
    const int w2   = wid & 1;
    const uint32_t qb = sbase + (uint32_t)(team * 5120);
    const uint32_t kb = sbase + 10240 + (uint32_t)(team * 5120);
    const uint32_t vb = sbase + 20480 + (uint32_t)(team * 4608);
    const float* bsm = dsm + BIAS_OFF / 4;   // [64][68]

    const float scale = 0.17677669529663687f;

    uint32_t qrow[2];
#pragma unroll
    for (int g = 0; g < 2; g++) qrow[g] = (uint32_t)((w2 * 32 + g * 16 + rsel + lr8) * 80);
    uint32_t krow[4];
#pragma unroll
    for (int p = 0; p < 4; p++) krow[p] = (uint32_t)((p * 16 + rsel + lr8) * 80);
    uint32_t vrow[2];
#pragma unroll
    for (int p = 0; p < 2; p++) vrow[p] = (uint32_t)((p * 16 + rsel + lr8) * 144);

    float sacc[2][8][4];
#pragma unroll
    for (int g = 0; g < 2; g++)
#pragma unroll
        for (int nt = 0; nt < 8; nt++)
#pragma unroll
            for (int r = 0; r < 4; r++) sacc[g][nt][r] = 0.0f;

#pragma unroll
    for (int kc = 0; kc < 2; kc++) {
        uint32_t af[2][4], bf[4][4];
#pragma unroll
        for (int g = 0; g < 2; g++)
            ldsm4(af[g], qb + qrow[g] + (uint32_t)((2 * kc + ksel) << 4));
#pragma unroll
        for (int p = 0; p < 4; p++)
            ldsm4(bf[p], kb + krow[p] + (uint32_t)((2 * kc + ksel) << 4));
#pragma unroll
        for (int g = 0; g < 2; g++)
#pragma unroll
            for (int p = 0; p < 4; p++) {
                mma_f16(sacc[g][2 * p],     af[g][0], af[g][1], af[g][2], af[g][3],
                        bf[p][0], bf[p][2]);
                mma_f16(sacc[g][2 * p + 1], af[g][0], af[g][1], af[g][2], af[g][3],
                        bf[p][1], bf[p][3]);
            }
    }

    // scale + bias (smem) + softmax (no max-subtraction)
#pragma unroll
    for (int g = 0; g < 2; g++) {
        int row0 = w2 * 32 + g * 16 + lrow;
#pragma unroll
        for (int nt = 0; nt < 8; nt++) {
            int col = nt * 8 + lcol * 2;
            float2 b0 = *(const float2*)(bsm + row0 * 68 + col);
            float2 b1 = *(const float2*)(bsm + (row0 + 8) * 68 + col);
            sacc[g][nt][0] = fmaf(sacc[g][nt][0], scale, b0.x);
            sacc[g][nt][1] = fmaf(sacc[g][nt][1], scale, b0.y);
            sacc[g][nt][2] = fmaf(sacc[g][nt][2], scale, b1.x);
            sacc[g][nt][3] = fmaf(sacc[g][nt][3], scale, b1.y);
        }
        float s0 = 0.0f, s1 = 0.0f;
#pragma unroll
        for (int nt = 0; nt < 8; nt++) {
            sacc[g][nt][0] = __expf(sacc[g][nt][0]); s0 += sacc[g][nt][0];
            sacc[g][nt][1] = __expf(sacc[g][nt][1]); s0 += sacc[g][nt][1];
            sacc[g][nt][2] = __expf(sacc[g][nt][2]); s1 += sacc[g][nt][2];
            sacc[g][nt][3] = __expf(sacc[g][nt][3]); s1 += sacc[g][nt][3];
        }
        s0 += __shfl_xor_sync(0xFFFFFFFFu, s0, 1);
        s0 += __shfl_xor_sync(0xFFFFFFFFu, s0, 2);
        s1 += __shfl_xor_sync(0xFFFFFFFFu, s1, 1);
        s1 += __shfl_xor_sync(0xFFFFFFFFu, s1, 2);
        float i0 = 1.0f / s0, i1 = 1.0f / s1;
#pragma unroll
        for (int nt = 0; nt < 8; nt++) {
            sacc[g][nt][0] *= i0; sacc[g][nt][1] *= i0;
            sacc[g][nt][2] *= i1; sacc[g][nt][3] *= i1;
        }
    }

    uint32_t pf[2][4][4];
#pragma unroll
    for (int g = 0; g < 2; g++)
#pragma unroll
        for (int kc = 0; kc < 4; kc++) {
            pf[g][kc][0] = h2u(__floats2half2_rn(sacc[g][2 * kc][0],     sacc[g][2 * kc][1]));
            pf[g][kc][1] = h2u(__floats2half2_rn(sacc[g][2 * kc][2],     sacc[g][2 * kc][3]));
            pf[g][kc][2] = h2u(__floats2half2_rn(sacc[g][2 * kc + 1][0], sacc[g][2 * kc + 1][1]));
            pf[g][kc][3] = h2u(__floats2half2_rn(sacc[g][2 * kc + 1][2], sacc[g][2 * kc + 1][3]));
        }

    float oacc[2][4][4];
#pragma unroll
    for (int g = 0; g < 2; g++)
#pragma unroll
        for (int nt = 0; nt < 4; nt++)
#pragma unroll
            for (int r = 0; r < 4; r++) oacc[g][nt][r] = 0.0f;

#pragma unroll
    for (int kc = 0; kc < 4; kc++) {
        uint32_t vf[2][4];
#pragma unroll
        for (int p = 0; p < 2; p++)
            ldsm4(vf[p], vb + vrow[p] + (uint32_t)((2 * kc + ksel) << 4));
#pragma unroll
        for (int g = 0; g < 2; g++) {
            mma_f16(oacc[g][0], pf[g][kc][0], pf[g][kc][1], pf[g][kc][2], pf[g][kc][3],
                    vf[0][0], vf[0][2]);
            mma_f16(oacc[g][1], pf[g][kc][0], pf[g][kc][1], pf[g][kc][2], pf[g][kc][3],
                    vf[0][1], vf[0][3]);
            mma_f16(oacc[g][2], pf[g][kc][0], pf[g][kc][1], pf[g][kc][2], pf[g][kc][3],
                    vf[1][0], vf[1][2]);
            mma_f16(oacc[g][3], pf[g][kc][0], pf[g][kc][1], pf[g][kc][2], pf[g][kc][3],
                    vf[1][1], vf[1][3]);
        }
    }
    {
        __half* og = g_attn16 + (size_t)(m0 + team * 64) * CDIM + h * HD;
#pragma unroll
        for (int g = 0; g < 2; g++) {
            int row0 = w2 * 32 + g * 16 + lrow;
#pragma unroll
            for (int nt = 0; nt < 4; nt++) {
                int col = nt * 8 + lcol * 2;
                *(uint32_t*)(og + (size_t)row0 * CDIM + col) =
                    h2u(__floats2half2_rn(oacc[g][nt][0], oacc[g][nt][1]));
                *(uint32_t*)(og + (size_t)(row0 + 8) * CDIM + col) =
                    h2u(__floats2half2_rn(oacc[g][nt][2], oacc[g][nt][3]));
            }
        }
    }
#undef STEP
#undef COMPUTE
#undef ISSUE
}

// ---------------------------------------------------------------------------
// proj GEMM (proven): 128 threads/4 warps, warp 64x48, CTA 128x96,
// 2-stage cp.async ring, occ 3. grid = (4 N-blocks fastest, 1024 M-blocks).
// ---------------------------------------------------------------------------
#define PNCH 6
#define PROJ_SMEM 57344

__global__ void __launch_bounds__(128, 3)
gemm_f16(const __half* __restrict__ A, const __half* __restrict__ Bt,
         const float* __restrict__ bias, float* __restrict__ out) {
    extern __shared__ float dsm[];

    const int t    = threadIdx.x;
    const int wid  = t >> 5, lane = t & 31;
    const int wm   = wid >> 1;
    const int wnn  = wid & 1;
    const int n0   = blockIdx.x * 96;
    const int m0   = blockIdx.y * 128;
    const int lrow = lane >> 2;
    const int lcol = lane & 3;

    const uint32_t sbase = smem_u32(dsm);
    const __half* Bn = Bt + (size_t)n0 * CDIM;

    float acc[4][6][4];
#pragma unroll
    for (int i = 0; i < 4; i++)
#pragma unroll
        for (int j = 0; j < 6; j++)
#pragma unroll
            for (int r = 0; r < 4; r++) acc[i][j][r] = 0.0f;

    const int ldr = t >> 3;
    const int ldg = t & 7;

    const int grp = lane >> 3, lr8 = lane & 7;
    const int rsel = (grp & 1) * 8;
    const int ksel = grp >> 1;

    uint32_t aoff[4]; int arl[4];
#pragma unroll
    for (int mt = 0; mt < 4; mt++) {
        int r = wm * 64 + mt * 16 + rsel + lr8;
        aoff[mt] = (uint32_t)(r << 7);
        arl[mt]  = r & 7;
    }
    uint32_t boff[3]; int brl[3];
#pragma unroll
    for (int p = 0; p < 3; p++) {
        int r = wnn * 48 + p * 16 + rsel + lr8;
        boff[p] = (uint32_t)(r << 7);
        brl[p]  = r & 7;
    }

#define ISSUE(ch, st) do {                                                              \
        int _k0 = (ch) * 64;                                                            \
        _Pragma("unroll")                                                               \
        for (int _i = 0; _i < 8; _i++) {                                                \
            int _row = ldr + _i * 16;                                                   \
            int _sg  = ldg ^ (_row & 7);                                                \
            cp16(sbase + (st) * 16384 + (uint32_t)((_row << 7) + (_sg << 4)),           \
                 A + (size_t)(m0 + _row) * CDIM + _k0 + ldg * 8);                       \
        }                                                                               \
        _Pragma("unroll")                                                               \
        for (int _i = 0; _i < 6; _i++) {                                                \
            int _row = ldr + _i * 16;                                                   \
            int _sg  = ldg ^ (_row & 7);                                                \
            cp16(sbase + 32768 + (st) * 12288 + (uint32_t)((_row << 7) + (_sg << 4)),   \
                 Bn + (size_t)_row * CDIM + _k0 + ldg * 8);                             \
        }                                                                               \
        CP_COMMIT();                                                                    \
    } while (0)

#define COMPUTE(st) do {                                                                \
        const uint32_t Aab = sbase + (st) * 16384;                                      \
        const uint32_t Bab = sbase + 32768 + (st) * 12288;                              \
        _Pragma("unroll")                                                               \
        for (int ks = 0; ks < 4; ks++) {                                                \
            uint32_t afr[4][4], bfr[3][4];                                              \
            _Pragma("unroll")                                                           \
            for (int mt = 0; mt < 4; mt++)                                              \
                ldsm4(afr[mt], Aab + aoff[mt] +                                         \
                      (uint32_t)(((2 * ks + ksel) ^ arl[mt]) << 4));                    \
            _Pragma("unroll")                                                           \
            for (int p = 0; p < 3; p++)                                                 \
                ldsm4(bfr[p], Bab + boff[p] +                                           \
                      (uint32_t)(((2 * ks + ksel) ^ brl[p]) << 4));                     \
            _Pragma("unroll")                                                           \
            for (int mt = 0; mt < 4; mt++) {                                            \
                _Pragma("unroll")                                                       \
                for (int p = 0; p < 3; p++) {                                           \
                    mma_f16(acc[mt][2 * p],     afr[mt][0], afr[mt][1], afr[mt][2],     \
                            afr[mt][3], bfr[p][0], bfr[p][2]);                          \
                    mma_f16(acc[mt][2 * p + 1], afr[mt][0], afr[mt][1], afr[mt][2],     \
                            afr[mt][3], bfr[p][1], bfr[p][3]);                          \
                }                                                                       \
            }                                                                           \
        }                                                                               \
    } while (0)

#define STEP(c) do {                                                                    \
        if ((c) == PNCH - 1) { CP_WAIT(0); } else { CP_WAIT(1); }                       \
        __syncthreads();                                                                \
        COMPUTE((c) & 1);                                                               \
        __syncthreads();                                                                \
        if ((c) + 2 < PNCH) ISSUE((c) + 2, (c) & 1);                                    \
    } while (0)

    ISSUE(0, 0);
    ISSUE(1, 1);
    STEP(0); STEP(1); STEP(2); STEP(3); STEP(4); STEP(5);

#pragma unroll
    for (int mt = 0; mt < 4; mt++) {
#pragma unroll
        for (int nt = 0; nt < 6; nt++) {
            int row = m0 + wm * 64 + mt * 16 + lrow;
            int col = n0 + wnn * 48 + nt * 8 + lcol * 2;
            float2 bv = *(const float2*)(bias + col);
            float2 o0, o1;
            o0.x = acc[mt][nt][0] + bv.x; o0.y = acc[mt][nt][1] + bv.y;
            o1.x = acc[mt][nt][2] + bv.x; o1.y = acc[mt][nt][3] + bv.y;
            *(float2*)(out + (size_t)row * CDIM + col)       = o0;
            *(float2*)(out + (size_t)(row + 8) * CDIM + col) = o1;
        }
    }
#undef STEP
#undef COMPUTE
#undef ISSUE
}

// ---------------------------------------------------------------------------
extern "C" void kernel_launch(void* const* d_in, const int* in_sizes, int n_in,
                              void* d_out, int out_size) {
    const float* x      = (const float*)d_in[0];
    const float* qkv_w  = (const float*)d_in[1];
    const float* qkv_b  = (const float*)d_in[2];
    const float* proj_w = (const float*)d_in[3];
    const float* proj_b = (const float*)d_in[4];
    const float* mlp_w1 = (const float*)d_in[5];
    const float* mlp_b1 = (const float*)d_in[6];
    const float* mlp_w2 = (const float*)d_in[7];
    const float* mlp_b2 = (const float*)d_in[8];

    __half* wt_proj; cudaGetSymbolAddress((void**)&wt_proj, g_wt_projh);
    __half* attn;    cudaGetSymbolAddress((void**)&attn,    g_attn16);
    __half* x16;     cudaGetSymbolAddress((void**)&x16,     g_x16);

    prep_kernel<<<PREP_BLOCKS, 256>>>(x, qkv_w, proj_w, mlp_w1, mlp_b1, mlp_w2, mlp_b2);

    cudaFuncSetAttribute(qkv_attn_kernel, cudaFuncAttributeMaxDynamicSharedMemorySize, FUSED_SMEM);
    cudaFuncSetAttribute(gemm_f16, cudaFuncAttributeMaxDynamicSharedMemorySize, PROJ_SMEM);

    // fused QKV GEMM + attention -> g_attn16 (fp16)
    qkv_attn_kernel<<<dim3(NH, MTOT / 128), 128, FUSED_SMEM>>>(x16, qkv_b);

    // projection GEMM: [131072,384] @ [384,384] -> d_out (fp32)
    gemm_f16<<<dim3(4, MTOT / 128), 128, PROJ_SMEM>>>(attn, wt_proj, proj_b, (float*)d_out);
}